// round 2
// baseline (speedup 1.0000x reference)
#include <cuda_runtime.h>
#include <math.h>

#define BB   8
#define LP   256
#define TMEL 1024
#define TG   256
#define MEL_C 80
#define HH   512
#define DH   64
#define LCN  512
#define TOUT 1536
#define KGG  31

// ---- scratch (floats) ----
#define MEL_OFF   0ul
#define Q_OFF     4194304ul
#define KV_OFF    5242880ul
#define CTX_OFF   13631488ul
#define ATTN_OFF  14680064ul
#define GA_OFF    15728640ul
#define GB_OFF    16777216ul
#define GT_OFF    17825792ul
#define WT_OFF    18874368ul
#define WT0_OFF   51380224ul
#define SCRATCH_FLOATS 52649984ul

__device__ float SCRATCH[SCRATCH_FLOATS];
__device__ int   LMAP[BB * TOUT];

// ---- transpose weights: src[o][c][31] -> dst[k][o][c] ----
__global__ void wtrans_kernel(const float* __restrict__ src, float* __restrict__ dst,
                              int O, int C)
{
    __shared__ float s[64 * 33];
    int o  = blockIdx.x;
    int cc = blockIdx.y * 64;
    int nc = min(64, C - cc);
    const float* p = src + ((size_t)o * C + cc) * KGG;
    for (int idx = threadIdx.x; idx < nc * KGG; idx += 256) {
        int c = idx / KGG, k = idx - c * KGG;
        s[c * 33 + k] = p[idx];
    }
    __syncthreads();
    for (int idx = threadIdx.x; idx < KGG * nc; idx += 256) {
        int k = idx / nc, c = idx - k * nc;
        dst[((size_t)k * O + o) * C + cc + c] = s[c * 33 + k];
    }
}

// ---- mel conv (K=3, 80->512) -> mel[b][t][h] ----
__global__ void melconv_kernel(const float* __restrict__ x,
                               const float* __restrict__ w,
                               const float* __restrict__ bias,
                               float* __restrict__ mel)
{
    __shared__ float Xs[MEL_C][66];
    int b = blockIdx.z, hbase = blockIdx.y * 128, t0 = blockIdx.x * 64;
    int tid = threadIdx.x;
    for (int idx = tid; idx < MEL_C * 66; idx += 512) {
        int c = idx / 66, j = idx - c * 66;
        int g = t0 + j - 1;
        Xs[c][j] = (g >= 0 && g < TMEL) ? x[((size_t)b * MEL_C + c) * TMEL + g] : 0.f;
    }
    __syncthreads();
    int hp = tid >> 3, tg = tid & 7;
    int h0 = hbase + hp * 2;
    float acc[2][8];
#pragma unroll
    for (int i = 0; i < 2; i++)
#pragma unroll
        for (int j = 0; j < 8; j++) acc[i][j] = 0.f;
    const float* w0 = w + (size_t)h0 * (MEL_C * 3);
    const float* w1 = w0 + MEL_C * 3;
    for (int c = 0; c < MEL_C; c++) {
#pragma unroll
        for (int k = 0; k < 3; k++) {
            float wa = w0[c * 3 + k], wb = w1[c * 3 + k];
#pragma unroll
            for (int j = 0; j < 8; j++) {
                float xv = Xs[c][tg + 8 * j + k];
                acc[0][j] += wa * xv;
                acc[1][j] += wb * xv;
            }
        }
    }
#pragma unroll
    for (int i = 0; i < 2; i++) {
        float bz = bias[h0 + i];
#pragma unroll
        for (int j = 0; j < 8; j++)
            mel[((size_t)b * TMEL + t0 + tg + 8 * j) * HH + h0 + i] = acc[i][j] + bz;
    }
}

// ---- GEMM: C[M,N] = A[M,K] @ W[N,K]^T + bias ----
__global__ void gemm_kernel(const float* __restrict__ A, const float* __restrict__ W,
                            const float* __restrict__ bias, float* __restrict__ C,
                            int M, int N, int K)
{
    __shared__ float As[16][68];
    __shared__ float Bs[16][68];
    int n0 = blockIdx.x * 64, m0 = blockIdx.y * 64;
    int tid = threadIdx.x;
    int tm = tid & 15, tn = tid >> 4;
    int lr = tid >> 2, lq = tid & 3;
    float acc[4][4];
#pragma unroll
    for (int i = 0; i < 4; i++)
#pragma unroll
        for (int j = 0; j < 4; j++) acc[i][j] = 0.f;
    for (int k0 = 0; k0 < K; k0 += 16) {
        float4 a4 = *(const float4*)&A[(size_t)(m0 + lr) * K + k0 + lq * 4];
        float4 b4 = *(const float4*)&W[(size_t)(n0 + lr) * K + k0 + lq * 4];
        As[lq * 4 + 0][lr] = a4.x; As[lq * 4 + 1][lr] = a4.y;
        As[lq * 4 + 2][lr] = a4.z; As[lq * 4 + 3][lr] = a4.w;
        Bs[lq * 4 + 0][lr] = b4.x; Bs[lq * 4 + 1][lr] = b4.y;
        Bs[lq * 4 + 2][lr] = b4.z; Bs[lq * 4 + 3][lr] = b4.w;
        __syncthreads();
#pragma unroll
        for (int k = 0; k < 16; k++) {
            float4 av = *(const float4*)&As[k][tm * 4];
            float4 bv = *(const float4*)&Bs[k][tn * 4];
            acc[0][0] += av.x * bv.x; acc[0][1] += av.x * bv.y; acc[0][2] += av.x * bv.z; acc[0][3] += av.x * bv.w;
            acc[1][0] += av.y * bv.x; acc[1][1] += av.y * bv.y; acc[1][2] += av.y * bv.z; acc[1][3] += av.y * bv.w;
            acc[2][0] += av.z * bv.x; acc[2][1] += av.z * bv.y; acc[2][2] += av.z * bv.z; acc[2][3] += av.z * bv.w;
            acc[3][0] += av.w * bv.x; acc[3][1] += av.w * bv.y; acc[3][2] += av.w * bv.z; acc[3][3] += av.w * bv.w;
        }
        __syncthreads();
    }
#pragma unroll
    for (int i = 0; i < 4; i++) {
        size_t row = (size_t)(m0 + tm * 4 + i) * N;
#pragma unroll
        for (int j = 0; j < 4; j++)
            C[row + n0 + tn * 4 + j] = acc[i][j] + bias[n0 + tn * 4 + j];
    }
}

// ---- flash attention ----
__global__ void attn_kernel(const float* __restrict__ q,
                            const float* __restrict__ kv,
                            float* __restrict__ ctx)
{
    __shared__ float Qs[64 * 64];
    __shared__ float Ks[32 * 64];
    __shared__ float Vs[32 * 64];
    __shared__ float Ps[64 * 32];
    int qt = blockIdx.x, h = blockIdx.y, b = blockIdx.z;
    int tid = threadIdx.x;
    int r = tid >> 2, cg = tid & 3;
    {
        int rr = tid >> 2, qq = tid & 3;
        const float* qp = q + (size_t)(b * LP + qt * 64 + rr) * HH + h * DH + qq * 16;
#pragma unroll
        for (int j = 0; j < 4; j++) {
            float4 v = *(const float4*)(qp + j * 4);
            v.x *= 0.125f; v.y *= 0.125f; v.z *= 0.125f; v.w *= 0.125f;
            *(float4*)&Qs[rr * 64 + qq * 16 + j * 4] = v;
        }
    }
    float m = -1e30f, l = 0.f;
    float acc[16];
#pragma unroll
    for (int d = 0; d < 16; d++) acc[d] = 0.f;

    for (int kt = 0; kt < TMEL / 32; kt++) {
        {
            int rr = tid >> 3, qq = tid & 7;
            const float* kp = kv + (size_t)(b * TMEL + kt * 32 + rr) * 1024 + h * DH + qq * 8;
            *(float4*)&Ks[rr * 64 + qq * 8]     = *(const float4*)(kp);
            *(float4*)&Ks[rr * 64 + qq * 8 + 4] = *(const float4*)(kp + 4);
            const float* vp = kp + 512;
            *(float4*)&Vs[rr * 64 + qq * 8]     = *(const float4*)(vp);
            *(float4*)&Vs[rr * 64 + qq * 8 + 4] = *(const float4*)(vp + 4);
        }
        __syncthreads();
        float s[8];
#pragma unroll
        for (int c = 0; c < 8; c++) s[c] = 0.f;
#pragma unroll
        for (int d4 = 0; d4 < 16; d4++) {
            float4 qv = *(const float4*)&Qs[r * 64 + d4 * 4];
#pragma unroll
            for (int c = 0; c < 8; c++) {
                float4 k4 = *(const float4*)&Ks[(cg * 8 + c) * 64 + d4 * 4];
                s[c] += qv.x * k4.x + qv.y * k4.y + qv.z * k4.z + qv.w * k4.w;
            }
        }
        float lm = s[0];
#pragma unroll
        for (int c = 1; c < 8; c++) lm = fmaxf(lm, s[c]);
        lm = fmaxf(lm, __shfl_xor_sync(0xffffffffu, lm, 1));
        lm = fmaxf(lm, __shfl_xor_sync(0xffffffffu, lm, 2));
        float mnew = fmaxf(m, lm);
        float p[8], ps = 0.f;
#pragma unroll
        for (int c = 0; c < 8; c++) { p[c] = __expf(s[c] - mnew); ps += p[c]; }
        ps += __shfl_xor_sync(0xffffffffu, ps, 1);
        ps += __shfl_xor_sync(0xffffffffu, ps, 2);
        float corr = __expf(m - mnew);
        l = l * corr + ps;
        m = mnew;
#pragma unroll
        for (int d = 0; d < 16; d++) acc[d] *= corr;
#pragma unroll
        for (int c = 0; c < 8; c++) Ps[r * 32 + cg * 8 + c] = p[c];
        __syncthreads();
#pragma unroll 8
        for (int kk = 0; kk < 32; kk++) {
            float pv = Ps[r * 32 + kk];
            const float* vrow = &Vs[kk * 64 + cg * 16];
            float4 v0 = *(const float4*)(vrow);
            float4 v1 = *(const float4*)(vrow + 4);
            float4 v2 = *(const float4*)(vrow + 8);
            float4 v3 = *(const float4*)(vrow + 12);
            acc[0]  += pv * v0.x; acc[1]  += pv * v0.y; acc[2]  += pv * v0.z; acc[3]  += pv * v0.w;
            acc[4]  += pv * v1.x; acc[5]  += pv * v1.y; acc[6]  += pv * v1.z; acc[7]  += pv * v1.w;
            acc[8]  += pv * v2.x; acc[9]  += pv * v2.y; acc[10] += pv * v2.z; acc[11] += pv * v2.w;
            acc[12] += pv * v3.x; acc[13] += pv * v3.y; acc[14] += pv * v3.z; acc[15] += pv * v3.w;
        }
        __syncthreads();
    }
    float inv = 1.f / l;
    float* op = ctx + (size_t)(b * LP + qt * 64 + r) * HH + h * DH + cg * 16;
#pragma unroll
    for (int j = 0; j < 4; j++) {
        float4 v;
        v.x = acc[j * 4 + 0] * inv; v.y = acc[j * 4 + 1] * inv;
        v.z = acc[j * 4 + 2] * inv; v.w = acc[j * 4 + 3] * inv;
        *(float4*)(op + j * 4) = v;
    }
}

// ---- conv K=31 as 31 shifted GEMMs, + bias + relu ----
// x: [B][C_IN][256], wt: [k][o][c] (o-stride=C_IN, k-stride=kstride), y: [B][512][256]
template <int C_IN>
__global__ void conv31_kernel(const float* __restrict__ x,
                              const float* __restrict__ wt, int kstride,
                              const float* __restrict__ bias,
                              float* __restrict__ y)
{
    constexpr int T = 256, TT = 128, CC = 16;
    __shared__ float Xs[CC][160];
    __shared__ float Ws[CC][68];
    int b = blockIdx.z, o0 = blockIdx.y * 64, t0 = blockIdx.x * TT;
    int tid = threadIdx.x;
    int to = tid >> 4, tt = tid & 15;
    float acc[4][8];
#pragma unroll
    for (int i = 0; i < 4; i++)
#pragma unroll
        for (int j = 0; j < 8; j++) acc[i][j] = 0.f;
    const float* xb = x + (size_t)b * C_IN * T;

    for (int cc = 0; cc < C_IN; cc += CC) {
        __syncthreads();
        for (int idx = tid; idx < CC * 160; idx += 256) {
            int c = idx / 160, j = idx - c * 160;
            int g = t0 + j - 15;
            float v = 0.f;
            if (j < TT + 30 && g >= 0 && g < T) v = xb[(size_t)(cc + c) * T + g];
            Xs[c][j] = v;
        }
        for (int k = 0; k < KGG; k++) {
            __syncthreads();
            {
                int o = tid >> 2, qq = tid & 3;
                const float* wp = wt + (size_t)k * kstride + (size_t)(o0 + o) * C_IN + cc + qq * 4;
                float4 w4 = *(const float4*)wp;
                Ws[qq * 4 + 0][o] = w4.x; Ws[qq * 4 + 1][o] = w4.y;
                Ws[qq * 4 + 2][o] = w4.z; Ws[qq * 4 + 3][o] = w4.w;
            }
            __syncthreads();
            int tb = tt + k;
#pragma unroll
            for (int c = 0; c < CC; c++) {
                float4 w4 = *(const float4*)&Ws[c][to * 4];
                float xv[8];
#pragma unroll
                for (int j = 0; j < 8; j++) xv[j] = Xs[c][tb + 16 * j];
#pragma unroll
                for (int j = 0; j < 8; j++) {
                    acc[0][j] += w4.x * xv[j];
                    acc[1][j] += w4.y * xv[j];
                    acc[2][j] += w4.z * xv[j];
                    acc[3][j] += w4.w * xv[j];
                }
            }
        }
    }
#pragma unroll
    for (int i = 0; i < 4; i++) {
        float bz = bias[o0 + to * 4 + i];
        float* yo = y + ((size_t)b * HH + o0 + to * 4 + i) * T + t0;
#pragma unroll
        for (int j = 0; j < 8; j++)
            yo[tt + 16 * j] = fmaxf(acc[i][j] + bz, 0.f);
    }
}

// ---- g transpose [B][512][256] -> [B][256][512] ----
__global__ void gtrans_kernel(const float* __restrict__ src, float* __restrict__ dst)
{
    __shared__ float s[32][33];
    int b = blockIdx.z;
    int c0 = blockIdx.y * 32, t0 = blockIdx.x * 32;
    int x = threadIdx.x, y = threadIdx.y;
    for (int i = y; i < 32; i += 8)
        s[i][x] = src[((size_t)b * HH + c0 + i) * 256 + t0 + x];
    __syncthreads();
    for (int i = y; i < 32; i += 8)
        dst[((size_t)b * TG + t0 + i) * HH + c0 + x] = s[x][i];
}

// ---- length-regulation map ----
__global__ void lmap_kernel(const int* __restrict__ tl)
{
    __shared__ int cum[LCN];
    int b = blockIdx.x, tid = threadIdx.x;
    int v = tl[b * LCN + tid];
    cum[tid] = v;
    __syncthreads();
    for (int off = 1; off < LCN; off <<= 1) {
        int t = (tid >= off) ? cum[tid - off] : 0;
        __syncthreads();
        cum[tid] += t;
        __syncthreads();
    }
    for (int t = tid; t < TOUT; t += LCN) LMAP[b * TOUT + t] = -1;
    __syncthreads();
    int end = cum[tid], start = end - v;
    for (int t = start; t < end; t++) LMAP[b * TOUT + t] = tid;
}

// ---- output gather ----
__global__ void gather_kernel(float* __restrict__ out,
                              const float* __restrict__ attn,
                              const float* __restrict__ gt)
{
    int b = blockIdx.y, t = blockIdx.x;
    int l = LMAP[b * TOUT + t];
    float4 v = make_float4(0.f, 0.f, 0.f, 0.f);
    if (l >= 0) {
        const float* src = (l < LP) ? attn + ((size_t)b * LP + l) * HH
                                    : gt + ((size_t)b * TG + (l - LP)) * HH;
        v = ((const float4*)src)[threadIdx.x];
    }
    ((float4*)(out + ((size_t)b * TOUT + t) * HH))[threadIdx.x] = v;
}

extern "C" void kernel_launch(void* const* d_in, const int* in_sizes, int n_in,
                              void* d_out, int out_size)
{
    const float* phone     = (const float*)d_in[0];
    const float* mel_spec  = (const float*)d_in[1];
    const float* gmel      = (const float*)d_in[2];
    const int*   tlen      = (const int*)d_in[3];
    const float* melw      = (const float*)d_in[4];
    const float* melb      = (const float*)d_in[5];
    const float* inpw      = (const float*)d_in[6];
    const float* inpb      = (const float*)d_in[7];
    const float* outw      = (const float*)d_in[8];
    const float* outb      = (const float*)d_in[9];
    const float* g0w       = (const float*)d_in[10];
    const float* g0b       = (const float*)d_in[11];
    const float* gws       = (const float*)d_in[12];
    const float* gbs       = (const float*)d_in[13];
    float* out = (float*)d_out;

    float* S;
    cudaGetSymbolAddress((void**)&S, SCRATCH);
    float* mel  = S + MEL_OFF;
    float* qbuf = S + Q_OFF;
    float* kv   = S + KV_OFF;
    float* ctx  = S + CTX_OFF;
    float* attn = S + ATTN_OFF;
    float* ga   = S + GA_OFF;
    float* gb   = S + GB_OFF;
    float* gt   = S + GT_OFF;
    float* wt   = S + WT_OFF;
    float* wt0  = S + WT0_OFF;

    // weight transposes
    wtrans_kernel<<<dim3(2048, 8), 256>>>(gws, wt, 2048, 512);
    wtrans_kernel<<<dim3(512, 2), 256>>>(g0w, wt0, 512, MEL_C);

    // mel conv -> mel[b][t][h]
    melconv_kernel<<<dim3(16, 4, 8), 512>>>(mel_spec, melw, melb, mel);

    // projections
    gemm_kernel<<<dim3(8, 32), 256>>>(phone, inpw, inpb, qbuf, BB * LP, HH, HH);
    gemm_kernel<<<dim3(16, 128), 256>>>(mel, inpw + (size_t)HH * HH, inpb + HH, kv,
                                        BB * TMEL, 2 * HH, HH);

    // attention
    attn_kernel<<<dim3(4, 8, 8), 256>>>(qbuf, kv, ctx);
    gemm_kernel<<<dim3(8, 32), 256>>>(ctx, outw, outb, attn, BB * LP, HH, HH);

    // g-conv stack
    conv31_kernel<MEL_C><<<dim3(2, 8, 8), 256>>>(gmel, wt0, 512 * MEL_C, g0b, ga);
    conv31_kernel<HH><<<dim3(2, 8, 8), 256>>>(ga, wt,                 2048 * 512, gbs,           gb);
    conv31_kernel<HH><<<dim3(2, 8, 8), 256>>>(gb, wt + 1 * 512 * 512, 2048 * 512, gbs + 1 * HH,  ga);
    conv31_kernel<HH><<<dim3(2, 8, 8), 256>>>(ga, wt + 2 * 512 * 512, 2048 * 512, gbs + 2 * HH,  gb);
    conv31_kernel<HH><<<dim3(2, 8, 8), 256>>>(gb, wt + 3 * 512 * 512, 2048 * 512, gbs + 3 * HH,  ga);

    gtrans_kernel<<<dim3(8, 16, 8), dim3(32, 8)>>>(ga, gt);

    // length regulation + gather
    lmap_kernel<<<8, LCN>>>(tlen);
    gather_kernel<<<dim3(TOUT, BB), 128>>>(out, attn, gt);
}

// round 4
// speedup vs baseline: 1.3932x; 1.3932x over previous
#include <cuda_runtime.h>
#include <math.h>

#define BB   8
#define LP   256
#define TMEL 1024
#define TG   256
#define MEL_C 80
#define HH   512
#define DH   64
#define LCN  512
#define TOUT 1536
#define KGG  31

typedef unsigned long long ull;

// ---- scratch (floats) ----
#define MEL_OFF   0ul
#define Q_OFF     4194304ul
#define KV_OFF    5242880ul
#define CTX_OFF   13631488ul
#define ATTN_OFF  14680064ul
#define GA_OFF    15728640ul
#define GB_OFF    16777216ul
#define GT_OFF    17825792ul
#define WT_OFF    18874368ul
#define WT0_OFF   51380224ul
#define SCRATCH_FLOATS 52649984ul

__device__ float SCRATCH[SCRATCH_FLOATS];
__device__ int   LMAP[BB * TOUT];

// ---- packed fp32 helpers ----
__device__ __forceinline__ void ffma2(ull& a, ull x, ull w) {
    asm("fma.rn.f32x2 %0, %1, %2, %0;" : "+l"(a) : "l"(x), "l"(w));
}
__device__ __forceinline__ ull dupf(float w) {
    ull r;
    asm("mov.b64 %0, {%1, %1};" : "=l"(r) : "f"(w));
    return r;
}

// ---- weight transpose: src[o][c][31] -> dst[k][c][o] (per layer via blockIdx.z) ----
__global__ void wtrans_kernel(const float* __restrict__ src, float* __restrict__ dst,
                              int O, int C)
{
    __shared__ float sbuf[64 * 125];
    int layer = blockIdx.z;
    src += (size_t)layer * O * C * KGG;
    dst += (size_t)layer * O * C * KGG;
    int o0 = blockIdx.x * 64;
    int cc = blockIdx.y * 4;
    for (int idx = threadIdx.x; idx < 64 * 124; idx += 256) {
        int o = idx / 124, r = idx - o * 124;
        sbuf[o * 125 + r] = src[((size_t)(o0 + o) * C + cc) * KGG + r];
    }
    __syncthreads();
    for (int idx = threadIdx.x; idx < KGG * 4 * 64; idx += 256) {
        int k = idx >> 8;
        int rem = idx & 255;
        int c = rem >> 6, o = rem & 63;
        dst[((size_t)k * C + cc + c) * O + o0 + o] = sbuf[o * 125 + c * 31 + k];
    }
}

// ---- mel conv (K=3, 80->512) -> mel[b][t][h] ----
__global__ void melconv_kernel(const float* __restrict__ x,
                               const float* __restrict__ w,
                               const float* __restrict__ bias,
                               float* __restrict__ mel)
{
    __shared__ float Xs[MEL_C][66];
    int b = blockIdx.z, hbase = blockIdx.y * 128, t0 = blockIdx.x * 64;
    int tid = threadIdx.x;
    for (int idx = tid; idx < MEL_C * 66; idx += 512) {
        int c = idx / 66, j = idx - c * 66;
        int g = t0 + j - 1;
        Xs[c][j] = (g >= 0 && g < TMEL) ? x[((size_t)b * MEL_C + c) * TMEL + g] : 0.f;
    }
    __syncthreads();
    int hp = tid >> 3, tg = tid & 7;
    int h0 = hbase + hp * 2;
    float acc[2][8];
#pragma unroll
    for (int i = 0; i < 2; i++)
#pragma unroll
        for (int j = 0; j < 8; j++) acc[i][j] = 0.f;
    const float* w0 = w + (size_t)h0 * (MEL_C * 3);
    const float* w1 = w0 + MEL_C * 3;
    for (int c = 0; c < MEL_C; c++) {
#pragma unroll
        for (int k = 0; k < 3; k++) {
            float wa = w0[c * 3 + k], wb = w1[c * 3 + k];
#pragma unroll
            for (int j = 0; j < 8; j++) {
                float xv = Xs[c][tg + 8 * j + k];
                acc[0][j] += wa * xv;
                acc[1][j] += wb * xv;
            }
        }
    }
#pragma unroll
    for (int i = 0; i < 2; i++) {
        float bz = bias[h0 + i];
#pragma unroll
        for (int j = 0; j < 8; j++)
            mel[((size_t)b * TMEL + t0 + tg + 8 * j) * HH + h0 + i] = acc[i][j] + bz;
    }
}

// ---- GEMM: C[M,N] = A[M,K] @ W[N,K]^T + bias ----
__global__ void gemm_kernel(const float* __restrict__ A, const float* __restrict__ W,
                            const float* __restrict__ bias, float* __restrict__ C,
                            int M, int N, int K)
{
    __shared__ float As[16][68];
    __shared__ float Bs[16][68];
    int n0 = blockIdx.x * 64, m0 = blockIdx.y * 64;
    int tid = threadIdx.x;
    int tm = tid & 15, tn = tid >> 4;
    int lr = tid >> 2, lq = tid & 3;
    float acc[4][4];
#pragma unroll
    for (int i = 0; i < 4; i++)
#pragma unroll
        for (int j = 0; j < 4; j++) acc[i][j] = 0.f;
    for (int k0 = 0; k0 < K; k0 += 16) {
        float4 a4 = *(const float4*)&A[(size_t)(m0 + lr) * K + k0 + lq * 4];
        float4 b4 = *(const float4*)&W[(size_t)(n0 + lr) * K + k0 + lq * 4];
        As[lq * 4 + 0][lr] = a4.x; As[lq * 4 + 1][lr] = a4.y;
        As[lq * 4 + 2][lr] = a4.z; As[lq * 4 + 3][lr] = a4.w;
        Bs[lq * 4 + 0][lr] = b4.x; Bs[lq * 4 + 1][lr] = b4.y;
        Bs[lq * 4 + 2][lr] = b4.z; Bs[lq * 4 + 3][lr] = b4.w;
        __syncthreads();
#pragma unroll
        for (int k = 0; k < 16; k++) {
            float4 av = *(const float4*)&As[k][tm * 4];
            float4 bv = *(const float4*)&Bs[k][tn * 4];
            acc[0][0] += av.x * bv.x; acc[0][1] += av.x * bv.y; acc[0][2] += av.x * bv.z; acc[0][3] += av.x * bv.w;
            acc[1][0] += av.y * bv.x; acc[1][1] += av.y * bv.y; acc[1][2] += av.y * bv.z; acc[1][3] += av.y * bv.w;
            acc[2][0] += av.z * bv.x; acc[2][1] += av.z * bv.y; acc[2][2] += av.z * bv.z; acc[2][3] += av.z * bv.w;
            acc[3][0] += av.w * bv.x; acc[3][1] += av.w * bv.y; acc[3][2] += av.w * bv.z; acc[3][3] += av.w * bv.w;
        }
        __syncthreads();
    }
#pragma unroll
    for (int i = 0; i < 4; i++) {
        size_t row = (size_t)(m0 + tm * 4 + i) * N;
#pragma unroll
        for (int j = 0; j < 4; j++)
            C[row + n0 + tn * 4 + j] = acc[i][j] + bias[n0 + tn * 4 + j];
    }
}

// ---- flash attention ----
__global__ void attn_kernel(const float* __restrict__ q,
                            const float* __restrict__ kv,
                            float* __restrict__ ctx)
{
    __shared__ float Qs[64 * 64];
    __shared__ float Ks[32 * 64];
    __shared__ float Vs[32 * 64];
    __shared__ float Ps[64 * 32];
    int qt = blockIdx.x, h = blockIdx.y, b = blockIdx.z;
    int tid = threadIdx.x;
    int r = tid >> 2, cg = tid & 3;
    {
        int rr = tid >> 2, qq = tid & 3;
        const float* qp = q + (size_t)(b * LP + qt * 64 + rr) * HH + h * DH + qq * 16;
#pragma unroll
        for (int j = 0; j < 4; j++) {
            float4 v = *(const float4*)(qp + j * 4);
            v.x *= 0.125f; v.y *= 0.125f; v.z *= 0.125f; v.w *= 0.125f;
            *(float4*)&Qs[rr * 64 + qq * 16 + j * 4] = v;
        }
    }
    float m = -1e30f, l = 0.f;
    float acc[16];
#pragma unroll
    for (int d = 0; d < 16; d++) acc[d] = 0.f;

    for (int kt = 0; kt < TMEL / 32; kt++) {
        {
            int rr = tid >> 3, qq = tid & 7;
            const float* kp = kv + (size_t)(b * TMEL + kt * 32 + rr) * 1024 + h * DH + qq * 8;
            *(float4*)&Ks[rr * 64 + qq * 8]     = *(const float4*)(kp);
            *(float4*)&Ks[rr * 64 + qq * 8 + 4] = *(const float4*)(kp + 4);
            const float* vp = kp + 512;
            *(float4*)&Vs[rr * 64 + qq * 8]     = *(const float4*)(vp);
            *(float4*)&Vs[rr * 64 + qq * 8 + 4] = *(const float4*)(vp + 4);
        }
        __syncthreads();
        float s[8];
#pragma unroll
        for (int c = 0; c < 8; c++) s[c] = 0.f;
#pragma unroll
        for (int d4 = 0; d4 < 16; d4++) {
            float4 qv = *(const float4*)&Qs[r * 64 + d4 * 4];
#pragma unroll
            for (int c = 0; c < 8; c++) {
                float4 k4 = *(const float4*)&Ks[(cg * 8 + c) * 64 + d4 * 4];
                s[c] += qv.x * k4.x + qv.y * k4.y + qv.z * k4.z + qv.w * k4.w;
            }
        }
        float lm = s[0];
#pragma unroll
        for (int c = 1; c < 8; c++) lm = fmaxf(lm, s[c]);
        lm = fmaxf(lm, __shfl_xor_sync(0xffffffffu, lm, 1));
        lm = fmaxf(lm, __shfl_xor_sync(0xffffffffu, lm, 2));
        float mnew = fmaxf(m, lm);
        float p[8], ps = 0.f;
#pragma unroll
        for (int c = 0; c < 8; c++) { p[c] = __expf(s[c] - mnew); ps += p[c]; }
        ps += __shfl_xor_sync(0xffffffffu, ps, 1);
        ps += __shfl_xor_sync(0xffffffffu, ps, 2);
        float corr = __expf(m - mnew);
        l = l * corr + ps;
        m = mnew;
#pragma unroll
        for (int d = 0; d < 16; d++) acc[d] *= corr;
#pragma unroll
        for (int c = 0; c < 8; c++) Ps[r * 32 + cg * 8 + c] = p[c];
        __syncthreads();
#pragma unroll 8
        for (int kk = 0; kk < 32; kk++) {
            float pv = Ps[r * 32 + kk];
            const float* vrow = &Vs[kk * 64 + cg * 16];
            float4 v0 = *(const float4*)(vrow);
            float4 v1 = *(const float4*)(vrow + 4);
            float4 v2 = *(const float4*)(vrow + 8);
            float4 v3 = *(const float4*)(vrow + 12);
            acc[0]  += pv * v0.x; acc[1]  += pv * v0.y; acc[2]  += pv * v0.z; acc[3]  += pv * v0.w;
            acc[4]  += pv * v1.x; acc[5]  += pv * v1.y; acc[6]  += pv * v1.z; acc[7]  += pv * v1.w;
            acc[8]  += pv * v2.x; acc[9]  += pv * v2.y; acc[10] += pv * v2.z; acc[11] += pv * v2.w;
            acc[12] += pv * v3.x; acc[13] += pv * v3.y; acc[14] += pv * v3.z; acc[15] += pv * v3.w;
        }
        __syncthreads();
    }
    float inv = 1.f / l;
    float* op = ctx + (size_t)(b * LP + qt * 64 + r) * HH + h * DH + cg * 16;
#pragma unroll
    for (int j = 0; j < 4; j++) {
        float4 v;
        v.x = acc[j * 4 + 0] * inv; v.y = acc[j * 4 + 1] * inv;
        v.z = acc[j * 4 + 2] * inv; v.w = acc[j * 4 + 3] * inv;
        *(float4*)(op + j * 4) = v;
    }
}

// ---- conv K=31, packed-f32x2 shifted-GEMM formulation ----
// x: [B][C_IN][256], wt: [31][C_IN][512], y: [B][512][256] (bias+relu)
// Block: 64 o x 128 t. Thread: 4 o x 4 t-pairs.
template <int C_IN>
__global__ __launch_bounds__(256) void conv31_kernel(
    const float* __restrict__ x,
    const float* __restrict__ wt,
    const float* __restrict__ bias,
    float* __restrict__ y)
{
    constexpr int T = 256, TT = 128, CC = 4, O = 512;
    __shared__ __align__(16) float Xs[2][CC][160];   // [1] = shifted-by-1 shadow
    __shared__ __align__(16) float Ws[KGG][CC][64];
    int b = blockIdx.z, o0 = blockIdx.y * 64, t0 = blockIdx.x * TT;
    int tid = threadIdx.x;
    int to = tid >> 4, tt = tid & 15;

    ull acc[4][4];
#pragma unroll
    for (int i = 0; i < 4; i++)
#pragma unroll
        for (int j = 0; j < 4; j++) acc[i][j] = 0ull;

    const float* xb = x + (size_t)b * C_IN * T;

    for (int cc = 0; cc < C_IN; cc += CC) {
        __syncthreads();
        for (int idx = tid; idx < CC * 160; idx += 256) {
            int c = idx / 160, j = idx - c * 160;
            int g = t0 + j - 15;
            const float* row = xb + (size_t)(cc + c) * T;
            Xs[0][c][j] = (g >= 0 && g < T) ? row[g] : 0.f;
            int g2 = g + 1;
            Xs[1][c][j] = (g2 >= 0 && g2 < T) ? row[g2] : 0.f;
        }
        for (int idx = tid; idx < KGG * CC * 16; idx += 256) {
            int k = idx >> 6;
            int rem = idx & 63;
            int c = rem >> 4, o4 = rem & 15;
            *(float4*)&Ws[k][c][o4 * 4] =
                *(const float4*)&wt[((size_t)k * C_IN + cc + c) * O + o0 + o4 * 4];
        }
        __syncthreads();

        for (int k = 0; k < KGG; k++) {
            const float* xbase = &Xs[k & 1][0][0] + (k & ~1) + 2 * tt;
#pragma unroll
            for (int c = 0; c < CC; c++) {
                float4 w4 = *(const float4*)&Ws[k][c][to * 4];
                ull wd0 = dupf(w4.x), wd1 = dupf(w4.y);
                ull wd2 = dupf(w4.z), wd3 = dupf(w4.w);
                const float* xrow = xbase + c * 160;
                ull x0 = *(const ull*)(xrow);
                ull x1 = *(const ull*)(xrow + 32);
                ull x2 = *(const ull*)(xrow + 64);
                ull x3 = *(const ull*)(xrow + 96);
                ffma2(acc[0][0], x0, wd0); ffma2(acc[0][1], x1, wd0);
                ffma2(acc[0][2], x2, wd0); ffma2(acc[0][3], x3, wd0);
                ffma2(acc[1][0], x0, wd1); ffma2(acc[1][1], x1, wd1);
                ffma2(acc[1][2], x2, wd1); ffma2(acc[1][3], x3, wd1);
                ffma2(acc[2][0], x0, wd2); ffma2(acc[2][1], x1, wd2);
                ffma2(acc[2][2], x2, wd2); ffma2(acc[2][3], x3, wd2);
                ffma2(acc[3][0], x0, wd3); ffma2(acc[3][1], x1, wd3);
                ffma2(acc[3][2], x2, wd3); ffma2(acc[3][3], x3, wd3);
            }
        }
    }
#pragma unroll
    for (int i = 0; i < 4; i++) {
        float bz = bias[o0 + to * 4 + i];
        float* yo = y + ((size_t)b * HH + o0 + to * 4 + i) * T + t0 + 2 * tt;
#pragma unroll
        for (int j = 0; j < 4; j++) {
            float2 v = *reinterpret_cast<float2*>(&acc[i][j]);
            v.x = fmaxf(v.x + bz, 0.f);
            v.y = fmaxf(v.y + bz, 0.f);
            *(float2*)(yo + 32 * j) = v;
        }
    }
}

// ---- g transpose [B][512][256] -> [B][256][512] ----
__global__ void gtrans_kernel(const float* __restrict__ src, float* __restrict__ dst)
{
    __shared__ float s[32][33];
    int b = blockIdx.z;
    int c0 = blockIdx.y * 32, t0 = blockIdx.x * 32;
    int x = threadIdx.x, y = threadIdx.y;
    for (int i = y; i < 32; i += 8)
        s[i][x] = src[((size_t)b * HH + c0 + i) * 256 + t0 + x];
    __syncthreads();
    for (int i = y; i < 32; i += 8)
        dst[((size_t)b * TG + t0 + i) * HH + c0 + x] = s[x][i];
}

// ---- length-regulation map ----
__global__ void lmap_kernel(const int* __restrict__ tl)
{
    __shared__ int cum[LCN];
    int b = blockIdx.x, tid = threadIdx.x;
    int v = tl[b * LCN + tid];
    cum[tid] = v;
    __syncthreads();
    for (int off = 1; off < LCN; off <<= 1) {
        int t = (tid >= off) ? cum[tid - off] : 0;
        __syncthreads();
        cum[tid] += t;
        __syncthreads();
    }
    for (int t = tid; t < TOUT; t += LCN) LMAP[b * TOUT + t] = -1;
    __syncthreads();
    int end = cum[tid], start = end - v;
    for (int t = start; t < end; t++) LMAP[b * TOUT + t] = tid;
}

// ---- output gather ----
__global__ void gather_kernel(float* __restrict__ out,
                              const float* __restrict__ attn,
                              const float* __restrict__ gt)
{
    int b = blockIdx.y, t = blockIdx.x;
    int l = LMAP[b * TOUT + t];
    float4 v = make_float4(0.f, 0.f, 0.f, 0.f);
    if (l >= 0) {
        const float* src = (l < LP) ? attn + ((size_t)b * LP + l) * HH
                                    : gt + ((size_t)b * TG + (l - LP)) * HH;
        v = ((const float4*)src)[threadIdx.x];
    }
    ((float4*)(out + ((size_t)b * TOUT + t) * HH))[threadIdx.x] = v;
}

extern "C" void kernel_launch(void* const* d_in, const int* in_sizes, int n_in,
                              void* d_out, int out_size)
{
    const float* phone     = (const float*)d_in[0];
    const float* mel_spec  = (const float*)d_in[1];
    const float* gmel      = (const float*)d_in[2];
    const int*   tlen      = (const int*)d_in[3];
    const float* melw      = (const float*)d_in[4];
    const float* melb      = (const float*)d_in[5];
    const float* inpw      = (const float*)d_in[6];
    const float* inpb      = (const float*)d_in[7];
    const float* outw      = (const float*)d_in[8];
    const float* outb      = (const float*)d_in[9];
    const float* g0w       = (const float*)d_in[10];
    const float* g0b       = (const float*)d_in[11];
    const float* gws       = (const float*)d_in[12];
    const float* gbs       = (const float*)d_in[13];
    float* out = (float*)d_out;

    float* S;
    cudaGetSymbolAddress((void**)&S, SCRATCH);
    float* mel  = S + MEL_OFF;
    float* qbuf = S + Q_OFF;
    float* kv   = S + KV_OFF;
    float* ctx  = S + CTX_OFF;
    float* attn = S + ATTN_OFF;
    float* ga   = S + GA_OFF;
    float* gb   = S + GB_OFF;
    float* gt   = S + GT_OFF;
    float* wt   = S + WT_OFF;
    float* wt0  = S + WT0_OFF;

    const size_t LSTRIDE = (size_t)KGG * HH * HH;   // per-layer wt stride

    // weight transposes -> [k][c][o]
    wtrans_kernel<<<dim3(8, 128, 4), 256>>>(gws, wt, HH, HH);
    wtrans_kernel<<<dim3(8, 20, 1), 256>>>(g0w, wt0, HH, MEL_C);

    // mel conv -> mel[b][t][h]
    melconv_kernel<<<dim3(16, 4, 8), 512>>>(mel_spec, melw, melb, mel);

    // projections
    gemm_kernel<<<dim3(8, 32), 256>>>(phone, inpw, inpb, qbuf, BB * LP, HH, HH);
    gemm_kernel<<<dim3(16, 128), 256>>>(mel, inpw + (size_t)HH * HH, inpb + HH, kv,
                                        BB * TMEL, 2 * HH, HH);

    // attention
    attn_kernel<<<dim3(4, 8, 8), 256>>>(qbuf, kv, ctx);
    gemm_kernel<<<dim3(8, 32), 256>>>(ctx, outw, outb, attn, BB * LP, HH, HH);

    // g-conv stack
    conv31_kernel<MEL_C><<<dim3(2, 8, 8), 256>>>(gmel, wt0, g0b, ga);
    conv31_kernel<HH><<<dim3(2, 8, 8), 256>>>(ga, wt + 0 * LSTRIDE, gbs + 0 * HH, gb);
    conv31_kernel<HH><<<dim3(2, 8, 8), 256>>>(gb, wt + 1 * LSTRIDE, gbs + 1 * HH, ga);
    conv31_kernel<HH><<<dim3(2, 8, 8), 256>>>(ga, wt + 2 * LSTRIDE, gbs + 2 * HH, gb);
    conv31_kernel<HH><<<dim3(2, 8, 8), 256>>>(gb, wt + 3 * LSTRIDE, gbs + 3 * HH, ga);

    gtrans_kernel<<<dim3(8, 16, 8), dim3(32, 8)>>>(ga, gt);

    // length regulation + gather
    lmap_kernel<<<8, LCN>>>(tlen);
    gather_kernel<<<dim3(TOUT, BB), 128>>>(out, attn, gt);
}